// round 1
// baseline (speedup 1.0000x reference)
#include <cuda_runtime.h>
#include <math.h>

#define BQ 8
#define SQ 2048
#define HQ 512
#define LQ 8
#define MQ 32
#define KBQ 256
#define SPLITS 8

// ---------------- scratch (device globals, allocation-free) ----------------
__device__ float  g_h [BQ*SQ*HQ];           // hidden state [B,S,H]
__device__ float  g_y [BQ*SQ*HQ];           // GEMM scratch
__device__ float  g_xf[BQ*SQ*HQ];           // fourier branch output
__device__ float2 g_tab[MQ*SQ];             // (cos, sin) of 2*pi*m*s/S
__device__ float  g_Xrp[SPLITS*BQ*MQ*HQ];
__device__ float  g_Xip[SPLITS*BQ*MQ*HQ];
__device__ float  g_Xr[BQ*MQ*HQ];
__device__ float  g_Xi[BQ*MQ*HQ];
__device__ float  g_Yr[BQ*MQ*HQ];
__device__ float  g_Yi[BQ*MQ*HQ];
__device__ float  g_o1[BQ*SQ*(HQ/2)];
__device__ float  g_o2[BQ*SQ*(HQ/4)];
__device__ float  g_gf[BQ*HQ];
__device__ float  g_k1[BQ*HQ];

__device__ __forceinline__ float gelu_exact(float x) {
    return 0.5f * x * (1.0f + erff(x * 0.70710678118654752440f));
}

// ---------------- DFT twiddle tables ----------------
__global__ void k_tab() {
    int i = blockIdx.x * blockDim.x + threadIdx.x;
    if (i < MQ * SQ) {
        int m = i / SQ, s = i % SQ;
        float a = (float)(m * s) * (1.0f / 1024.0f);  // theta/pi = 2*m*s/S
        g_tab[i] = make_float2(cospif(a), sinpif(a));
    }
}

// ---------------- input projection: h = x*in_w + in_b ----------------
__global__ void k_init(const float* __restrict__ x, const float* __restrict__ in_w,
                       const float* __restrict__ in_b) {
    int i = blockIdx.x * 256 + threadIdx.x;
    if (i < BQ * SQ * HQ) {
        int c  = i & (HQ - 1);
        int bs = i >> 9;
        g_h[i] = x[bs] * in_w[c] + in_b[c];
    }
}

// ---------------- forward DFT (first 32 modes), split over s ----------------
// grid (B*(H/128), SPLITS), block 128
__global__ void k_dftf() {
    int tid = threadIdx.x;
    int b  = blockIdx.x >> 2;
    int c  = (blockIdx.x & 3) * 128 + tid;
    int s0 = blockIdx.y * (SQ / SPLITS);          // 256 s per block
    float fr[MQ], fi[MQ];
#pragma unroll
    for (int m = 0; m < MQ; m++) { fr[m] = 0.f; fi[m] = 0.f; }
    __shared__ float2 tb[MQ * 64];
    for (int sch = 0; sch < 4; sch++) {
        int sb = s0 + sch * 64;
        __syncthreads();
        for (int i = tid; i < MQ * 64; i += 128) {
            int m = i >> 6, ss = i & 63;
            tb[i] = g_tab[m * SQ + sb + ss];
        }
        __syncthreads();
        for (int ss = 0; ss < 64; ss++) {
            float hv = g_h[(b * SQ + sb + ss) * HQ + c];
#pragma unroll
            for (int m = 0; m < MQ; m++) {
                float2 t = tb[m * 64 + ss];
                fr[m] = fmaf(hv,  t.x, fr[m]);
                fi[m] = fmaf(-hv, t.y, fi[m]);
            }
        }
    }
    int base = blockIdx.y * (BQ * MQ * HQ) + b * MQ * HQ + c;
#pragma unroll
    for (int m = 0; m < MQ; m++) {
        g_Xrp[base + m * HQ] = fr[m];
        g_Xip[base + m * HQ] = fi[m];
    }
}

__global__ void k_dftred() {
    int i = blockIdx.x * 256 + threadIdx.x;
    if (i < BQ * MQ * HQ) {
        float sr = 0.f, si = 0.f;
#pragma unroll
        for (int sp = 0; sp < SPLITS; sp++) {
            sr += g_Xrp[sp * (BQ * MQ * HQ) + i];
            si += g_Xip[sp * (BQ * MQ * HQ) + i];
        }
        g_Xr[i] = sr;
        g_Xi[i] = si;
    }
}

// ---------------- per-mode complex GEMM: Y[b,m,:] = X[b,m,:] @ Wc[m] ----------------
// grid (32 modes, 4 k-tiles), block 128
__global__ void k_spec(const float* __restrict__ Wr, const float* __restrict__ Wi) {
    int m = blockIdx.x, tid = threadIdx.x;
    __shared__ float sXr[BQ][HQ];
    __shared__ float sXi[BQ][HQ];
    for (int i = tid; i < BQ * HQ; i += 128) {
        int b = i >> 9, hh = i & 511;
        sXr[b][hh] = g_Xr[(b * MQ + m) * HQ + hh];
        sXi[b][hh] = g_Xi[(b * MQ + m) * HQ + hh];
    }
    __syncthreads();
    int k = blockIdx.y * 128 + tid;
    float yr[BQ], yi[BQ];
#pragma unroll
    for (int b = 0; b < BQ; b++) { yr[b] = 0.f; yi[b] = 0.f; }
    for (int h = 0; h < HQ; h++) {
        float wr = Wr[(m * HQ + h) * HQ + k];
        float wi = Wi[(m * HQ + h) * HQ + k];
#pragma unroll
        for (int b = 0; b < BQ; b++) {
            float xr = sXr[b][h], xi = sXi[b][h];
            yr[b] = fmaf(xr, wr, fmaf(-xi, wi, yr[b]));
            yi[b] = fmaf(xr, wi, fmaf( xi, wr, yi[b]));
        }
    }
#pragma unroll
    for (int b = 0; b < BQ; b++) {
        g_Yr[(b * MQ + m) * HQ + k] = yr[b];
        g_Yi[(b * MQ + m) * HQ + k] = yi[b];
    }
}

// ---------------- inverse DFT (irfft with only modes 0..31 nonzero) ----------------
// grid (S/256, B*4), block 128
__global__ void k_idft() {
    int tid = threadIdx.x;
    int b = blockIdx.y >> 2;
    int c = (blockIdx.y & 3) * 128 + tid;
    float yr[MQ], yi[MQ];
#pragma unroll
    for (int m = 0; m < MQ; m++) {
        yr[m] = g_Yr[(b * MQ + m) * HQ + c];
        yi[m] = g_Yi[(b * MQ + m) * HQ + c];
    }
    __shared__ float2 tb[MQ * 64];
    int s0 = blockIdx.x * 256;
    for (int sch = 0; sch < 4; sch++) {
        int sb = s0 + sch * 64;
        __syncthreads();
        for (int i = tid; i < MQ * 64; i += 128) {
            int m = i >> 6, ss = i & 63;
            tb[i] = g_tab[m * SQ + sb + ss];
        }
        __syncthreads();
        for (int ss = 0; ss < 64; ss++) {
            float acc = 0.f;
#pragma unroll
            for (int m = 1; m < MQ; m++) {
                float2 t = tb[m * 64 + ss];
                acc = fmaf(yr[m],  t.x, acc);
                acc = fmaf(-yi[m], t.y, acc);
            }
            g_xf[(b * SQ + sb + ss) * HQ + c] = (yr[0] + 2.f * acc) * (1.0f / (float)SQ);
        }
    }
}

// ---------------- generic fp32 GEMM: C[M,N] = A[M,K] @ W[N,K]^T ----------------
// BM=BN=64, BK=16, 256 threads, 4x4 microtile
__global__ void k_gemm(const float* __restrict__ A, const float* __restrict__ W,
                       float* __restrict__ C, int M, int N, int K) {
    __shared__ __align__(16) float As[16 * 68];
    __shared__ __align__(16) float Bs[16 * 68];
    int tid = threadIdx.x;
    int tx = tid & 15, ty = tid >> 4;
    int i0 = blockIdx.x * 64, n0 = blockIdx.y * 64;
    int kk0 = tid & 15, r0 = tid >> 4;
    float acc[4][4] = {};
    for (int k0 = 0; k0 < K; k0 += 16) {
#pragma unroll
        for (int i = 0; i < 4; i++) {
            int r = r0 + i * 16;
            As[kk0 * 68 + r] = A[(size_t)(i0 + r) * K + k0 + kk0];
            Bs[kk0 * 68 + r] = W[(size_t)(n0 + r) * K + k0 + kk0];
        }
        __syncthreads();
#pragma unroll
        for (int kk = 0; kk < 16; kk++) {
            float4 a = *(const float4*)&As[kk * 68 + ty * 4];
            float4 b = *(const float4*)&Bs[kk * 68 + tx * 4];
            acc[0][0] = fmaf(a.x, b.x, acc[0][0]); acc[0][1] = fmaf(a.x, b.y, acc[0][1]);
            acc[0][2] = fmaf(a.x, b.z, acc[0][2]); acc[0][3] = fmaf(a.x, b.w, acc[0][3]);
            acc[1][0] = fmaf(a.y, b.x, acc[1][0]); acc[1][1] = fmaf(a.y, b.y, acc[1][1]);
            acc[1][2] = fmaf(a.y, b.z, acc[1][2]); acc[1][3] = fmaf(a.y, b.w, acc[1][3]);
            acc[2][0] = fmaf(a.z, b.x, acc[2][0]); acc[2][1] = fmaf(a.z, b.y, acc[2][1]);
            acc[2][2] = fmaf(a.z, b.z, acc[2][2]); acc[2][3] = fmaf(a.z, b.w, acc[2][3]);
            acc[3][0] = fmaf(a.w, b.x, acc[3][0]); acc[3][1] = fmaf(a.w, b.y, acc[3][1]);
            acc[3][2] = fmaf(a.w, b.z, acc[3][2]); acc[3][3] = fmaf(a.w, b.w, acc[3][3]);
        }
        __syncthreads();
    }
#pragma unroll
    for (int i = 0; i < 4; i++) {
        float4 v = make_float4(acc[i][0], acc[i][1], acc[i][2], acc[i][3]);
        *(float4*)&C[(size_t)(i0 + ty * 4 + i) * N + n0 + tx * 4] = v;
    }
}

// ---------------- fused: y += conv_b + xf ; LayerNorm ; h = LN*g+b + h ----------------
// grid 16384 rows, block 128
__global__ void k_ln(const float* __restrict__ cb, const float* __restrict__ gg,
                     const float* __restrict__ bb) {
    int row = blockIdx.x, tid = threadIdx.x;
    float v[4], s = 0.f, s2 = 0.f;
#pragma unroll
    for (int i = 0; i < 4; i++) {
        int j = tid + i * 128;
        float t = g_y[(size_t)row * HQ + j] + g_xf[(size_t)row * HQ + j] + cb[j];
        v[i] = t; s += t; s2 += t * t;
    }
#pragma unroll
    for (int o = 16; o; o >>= 1) {
        s  += __shfl_xor_sync(0xffffffffu, s,  o);
        s2 += __shfl_xor_sync(0xffffffffu, s2, o);
    }
    __shared__ float red[64];
    int w = tid >> 5;
    if ((tid & 31) == 0) { red[w] = s; red[32 + w] = s2; }
    __syncthreads();
    float ts  = red[0] + red[1] + red[2] + red[3];
    float ts2 = red[32] + red[33] + red[34] + red[35];
    float mu  = ts * (1.f / HQ);
    float var = ts2 * (1.f / HQ) - mu * mu;
    float rinv = rsqrtf(var + 1e-5f);
#pragma unroll
    for (int i = 0; i < 4; i++) {
        int j = tid + i * 128;
        size_t idx = (size_t)row * HQ + j;
        g_h[idx] = (v[i] - mu) * rinv * gg[j] + bb[j] + g_h[idx];
    }
}

// ---------------- bias + GELU ----------------
__global__ void k_biasgelu(const float* __restrict__ in, float* __restrict__ out,
                           const float* __restrict__ bias, int nmask, int total) {
    int i = blockIdx.x * 256 + threadIdx.x;
    if (i < total) out[i] = gelu_exact(in[i] + bias[i & nmask]);
}

// ---------------- final projection to scalar ----------------
__global__ void k_op3(const float* __restrict__ w, const float* __restrict__ b3,
                      float* __restrict__ out) {
    int tid = threadIdx.x;
    int row = blockIdx.x * 4 + (tid >> 5);
    int lane = tid & 31;
    float s = 0.f;
#pragma unroll
    for (int i = 0; i < 4; i++) {
        int j = lane + i * 32;
        s += g_o2[(size_t)row * 128 + j] * w[j];
    }
#pragma unroll
    for (int o = 16; o; o >>= 1) s += __shfl_xor_sync(0xffffffffu, s, o);
    if (lane == 0) out[row] = s + b3[0];
}

// ---------------- mean over s ----------------
__global__ void k_mean() {
    int b = blockIdx.x >> 2;
    int c = (blockIdx.x & 3) * 128 + threadIdx.x;
    float s = 0.f;
    for (int ss = 0; ss < SQ; ss++) s += g_h[(size_t)(b * SQ + ss) * HQ + c];
    g_gf[b * HQ + c] = s * (1.f / SQ);
}

// ---------------- head: k1 = gelu(gf @ h1_w^T + h1_b) ----------------
__global__ void k_head1(const float* __restrict__ w, const float* __restrict__ bias) {
    int b = blockIdx.x, tid = threadIdx.x;
    int j = blockIdx.y * 128 + tid;
    __shared__ float sg[HQ];
    for (int i = tid; i < HQ; i += 128) sg[i] = g_gf[b * HQ + i];
    __syncthreads();
    const float4* w4 = (const float4*)(w + (size_t)j * HQ);
    float acc = 0.f;
    for (int c = 0; c < HQ / 4; c++) {
        float4 wv = w4[c];
        float4 gv = *(const float4*)&sg[c * 4];
        acc = fmaf(wv.x, gv.x, acc); acc = fmaf(wv.y, gv.y, acc);
        acc = fmaf(wv.z, gv.z, acc); acc = fmaf(wv.w, gv.w, acc);
    }
    g_k1[b * HQ + j] = gelu_exact(acc + bias[j]);
}

// ---------------- head: key_pred = sigmoid(k1 @ h2_w^T + h2_b) ----------------
__global__ void k_head2(const float* __restrict__ w, const float* __restrict__ bias,
                        float* __restrict__ out) {
    int b = blockIdx.x, tid = threadIdx.x;
    int j = blockIdx.y * 128 + tid;
    __shared__ float sk[HQ];
    for (int i = tid; i < HQ; i += 128) sk[i] = g_k1[b * HQ + i];
    __syncthreads();
    const float4* w4 = (const float4*)(w + (size_t)j * HQ);
    float acc = 0.f;
    for (int c = 0; c < HQ / 4; c++) {
        float4 wv = w4[c];
        float4 kv = *(const float4*)&sk[c * 4];
        acc = fmaf(wv.x, kv.x, acc); acc = fmaf(wv.y, kv.y, acc);
        acc = fmaf(wv.z, kv.z, acc); acc = fmaf(wv.w, kv.w, acc);
    }
    float t = acc + bias[j];
    out[BQ * SQ + b * KBQ + j] = 1.f / (1.f + expf(-t));
}

// ---------------- launch ----------------
extern "C" void kernel_launch(void* const* d_in, const int* in_sizes, int n_in,
                              void* d_out, int out_size) {
    const float* x      = (const float*)d_in[0];
    const float* in_w   = (const float*)d_in[1];
    const float* in_b   = (const float*)d_in[2];
    const float* fw_r   = (const float*)d_in[3];
    const float* fw_i   = (const float*)d_in[4];
    const float* conv_w = (const float*)d_in[5];
    const float* conv_b = (const float*)d_in[6];
    const float* ln_g   = (const float*)d_in[7];
    const float* ln_b   = (const float*)d_in[8];
    const float* op1_w  = (const float*)d_in[9];
    const float* op1_b  = (const float*)d_in[10];
    const float* op2_w  = (const float*)d_in[11];
    const float* op2_b  = (const float*)d_in[12];
    const float* op3_w  = (const float*)d_in[13];
    const float* op3_b  = (const float*)d_in[14];
    const float* h1_w   = (const float*)d_in[15];
    const float* h1_b   = (const float*)d_in[16];
    const float* h2_w   = (const float*)d_in[17];
    const float* h2_b   = (const float*)d_in[18];
    float* out = (float*)d_out;

    float *hp, *yp, *xfp, *o1p, *o2p;
    cudaGetSymbolAddress((void**)&hp,  g_h);
    cudaGetSymbolAddress((void**)&yp,  g_y);
    cudaGetSymbolAddress((void**)&xfp, g_xf);
    cudaGetSymbolAddress((void**)&o1p, g_o1);
    cudaGetSymbolAddress((void**)&o2p, g_o2);

    k_tab<<<(MQ * SQ + 255) / 256, 256>>>();
    k_init<<<(BQ * SQ * HQ + 255) / 256, 256>>>(x, in_w, in_b);

    for (int l = 0; l < LQ; l++) {
        k_dftf<<<dim3(BQ * (HQ / 128), SPLITS), 128>>>();
        k_dftred<<<(BQ * MQ * HQ + 255) / 256, 256>>>();
        k_spec<<<dim3(MQ, HQ / 128), 128>>>(fw_r + (size_t)l * MQ * HQ * HQ,
                                            fw_i + (size_t)l * MQ * HQ * HQ);
        k_idft<<<dim3(SQ / 256, BQ * 4), 128>>>();
        k_gemm<<<dim3(BQ * SQ / 64, HQ / 64), 256>>>(hp, conv_w + (size_t)l * HQ * HQ,
                                                     yp, BQ * SQ, HQ, HQ);
        k_ln<<<BQ * SQ, 128>>>(conv_b + l * HQ, ln_g + l * HQ, ln_b + l * HQ);
    }

    // output projection: H -> H/2 -> H/4 -> 1
    k_gemm<<<dim3(BQ * SQ / 64, (HQ / 2) / 64), 256>>>(hp, op1_w, yp, BQ * SQ, HQ / 2, HQ);
    k_biasgelu<<<(BQ * SQ * (HQ / 2) + 255) / 256, 256>>>(yp, o1p, op1_b, HQ / 2 - 1,
                                                          BQ * SQ * (HQ / 2));
    k_gemm<<<dim3(BQ * SQ / 64, (HQ / 4) / 64), 256>>>(o1p, op2_w, yp, BQ * SQ, HQ / 4, HQ / 2);
    k_biasgelu<<<(BQ * SQ * (HQ / 4) + 255) / 256, 256>>>(yp, o2p, op2_b, HQ / 4 - 1,
                                                          BQ * SQ * (HQ / 4));
    k_op3<<<BQ * SQ / 4, 128>>>(op3_w, op3_b, out);

    // cryptanalytic head
    k_mean<<<BQ * 4, 128>>>();
    k_head1<<<dim3(BQ, HQ / 128), 128>>>(h1_w, h1_b);
    k_head2<<<dim3(BQ, KBQ / 128), 128>>>(h2_w, h2_b, out);
}

// round 5
// speedup vs baseline: 1.1981x; 1.1981x over previous
#include <cuda_runtime.h>
#include <cstdint>
#include <stdint.h>
#include <math.h>

#define BQ 8
#define SQ 2048
#define HQ 512
#define LQ 8
#define MQ 32
#define KBQ 256
#define SPLITS 8

// ---------------- scratch (device globals, allocation-free) ----------------
__device__ float  g_h [BQ*SQ*HQ];           // hidden state [B,S,H]
__device__ float  g_y [BQ*SQ*HQ];           // GEMM scratch
__device__ float  g_xf[BQ*SQ*HQ];           // fourier branch output
__device__ float2 g_tab[MQ*SQ];             // (cos, sin) of 2*pi*m*s/S
__device__ float  g_Xrp[SPLITS*BQ*MQ*HQ];
__device__ float  g_Xip[SPLITS*BQ*MQ*HQ];
__device__ float  g_Xr[BQ*MQ*HQ];
__device__ float  g_Xi[BQ*MQ*HQ];
__device__ float  g_Yr[BQ*MQ*HQ];
__device__ float  g_Yi[BQ*MQ*HQ];
__device__ float  g_o1[BQ*SQ*(HQ/2)];
__device__ float  g_o2[BQ*SQ*(HQ/4)];
__device__ float  g_gf[BQ*HQ];
__device__ float  g_k1[BQ*HQ];

__device__ __forceinline__ float gelu_exact(float x) {
    return 0.5f * x * (1.0f + erff(x * 0.70710678118654752440f));
}

// ---------------- tf32 helpers ----------------
__device__ __forceinline__ unsigned int f2tf32(float fval) {
    unsigned int rr;
    asm("cvt.rna.tf32.f32 %0, %1;" : "=r"(rr) : "f"(fval));
    return rr;
}

__device__ __forceinline__ void ldsm4(unsigned int& ra, unsigned int& rb,
                                      unsigned int& rc, unsigned int& rd,
                                      unsigned int addr) {
    asm volatile("ldmatrix.sync.aligned.m8n8.x4.shared.b16 {%0,%1,%2,%3}, [%4];"
                 : "=r"(ra), "=r"(rb), "=r"(rc), "=r"(rd) : "r"(addr));
}

__device__ __forceinline__ void mma_tf32(float* dacc, const unsigned int* amat,
                                         const unsigned int* bmat) {
    asm volatile(
        "mma.sync.aligned.m16n8k8.row.col.f32.tf32.tf32.f32 "
        "{%0,%1,%2,%3}, {%4,%5,%6,%7}, {%8,%9}, {%0,%1,%2,%3};"
        : "+f"(dacc[0]), "+f"(dacc[1]), "+f"(dacc[2]), "+f"(dacc[3])
        : "r"(amat[0]), "r"(amat[1]), "r"(amat[2]), "r"(amat[3]),
          "r"(bmat[0]), "r"(bmat[1]));
}

// ---------------- DFT twiddle tables ----------------
__global__ void k_tab() {
    int i = blockIdx.x * blockDim.x + threadIdx.x;
    if (i < MQ * SQ) {
        int m = i / SQ, s = i % SQ;
        float a = (float)(m * s) * (1.0f / 1024.0f);  // theta/pi = 2*m*s/S
        g_tab[i] = make_float2(cospif(a), sinpif(a));
    }
}

// ---------------- input projection: h = x*in_w + in_b ----------------
__global__ void k_init(const float* __restrict__ x, const float* __restrict__ in_w,
                       const float* __restrict__ in_b) {
    int i = blockIdx.x * 256 + threadIdx.x;
    if (i < BQ * SQ * HQ) {
        int c  = i & (HQ - 1);
        int bs = i >> 9;
        g_h[i] = x[bs] * in_w[c] + in_b[c];
    }
}

// ---------------- forward DFT (first 32 modes), split over s ----------------
__global__ void k_dftf() {
    int tid = threadIdx.x;
    int b  = blockIdx.x >> 2;
    int c  = (blockIdx.x & 3) * 128 + tid;
    int s0 = blockIdx.y * (SQ / SPLITS);
    float fr[MQ], fi[MQ];
#pragma unroll
    for (int m = 0; m < MQ; m++) { fr[m] = 0.f; fi[m] = 0.f; }
    __shared__ float2 tb[MQ * 64];
    for (int sch = 0; sch < 4; sch++) {
        int sb = s0 + sch * 64;
        __syncthreads();
        for (int i = tid; i < MQ * 64; i += 128) {
            int m = i >> 6, ss = i & 63;
            tb[i] = g_tab[m * SQ + sb + ss];
        }
        __syncthreads();
        for (int ss = 0; ss < 64; ss++) {
            float hv = g_h[(b * SQ + sb + ss) * HQ + c];
#pragma unroll
            for (int m = 0; m < MQ; m++) {
                float2 t = tb[m * 64 + ss];
                fr[m] = fmaf(hv,  t.x, fr[m]);
                fi[m] = fmaf(-hv, t.y, fi[m]);
            }
        }
    }
    int base = blockIdx.y * (BQ * MQ * HQ) + b * MQ * HQ + c;
#pragma unroll
    for (int m = 0; m < MQ; m++) {
        g_Xrp[base + m * HQ] = fr[m];
        g_Xip[base + m * HQ] = fi[m];
    }
}

__global__ void k_dftred() {
    int i = blockIdx.x * 256 + threadIdx.x;
    if (i < BQ * MQ * HQ) {
        float sr = 0.f, si = 0.f;
#pragma unroll
        for (int sp = 0; sp < SPLITS; sp++) {
            sr += g_Xrp[sp * (BQ * MQ * HQ) + i];
            si += g_Xip[sp * (BQ * MQ * HQ) + i];
        }
        g_Xr[i] = sr;
        g_Xi[i] = si;
    }
}

// ---------------- per-mode complex GEMM ----------------
__global__ void k_spec(const float* __restrict__ Wr, const float* __restrict__ Wi) {
    int m = blockIdx.x, tid = threadIdx.x;
    __shared__ float sXr[BQ][HQ];
    __shared__ float sXi[BQ][HQ];
    for (int i = tid; i < BQ * HQ; i += 128) {
        int b = i >> 9, hh = i & 511;
        sXr[b][hh] = g_Xr[(b * MQ + m) * HQ + hh];
        sXi[b][hh] = g_Xi[(b * MQ + m) * HQ + hh];
    }
    __syncthreads();
    int k = blockIdx.y * 128 + tid;
    float yr[BQ], yi[BQ];
#pragma unroll
    for (int b = 0; b < BQ; b++) { yr[b] = 0.f; yi[b] = 0.f; }
    for (int h = 0; h < HQ; h++) {
        float wr = Wr[(m * HQ + h) * HQ + k];
        float wi = Wi[(m * HQ + h) * HQ + k];
#pragma unroll
        for (int b = 0; b < BQ; b++) {
            float xr = sXr[b][h], xi = sXi[b][h];
            yr[b] = fmaf(xr, wr, fmaf(-xi, wi, yr[b]));
            yi[b] = fmaf(xr, wi, fmaf( xi, wr, yi[b]));
        }
    }
#pragma unroll
    for (int b = 0; b < BQ; b++) {
        g_Yr[(b * MQ + m) * HQ + k] = yr[b];
        g_Yi[(b * MQ + m) * HQ + k] = yi[b];
    }
}

// ---------------- inverse DFT ----------------
__global__ void k_idft() {
    int tid = threadIdx.x;
    int b = blockIdx.y >> 2;
    int c = (blockIdx.y & 3) * 128 + tid;
    float yr[MQ], yi[MQ];
#pragma unroll
    for (int m = 0; m < MQ; m++) {
        yr[m] = g_Yr[(b * MQ + m) * HQ + c];
        yi[m] = g_Yi[(b * MQ + m) * HQ + c];
    }
    __shared__ float2 tb[MQ * 64];
    int s0 = blockIdx.x * 256;
    for (int sch = 0; sch < 4; sch++) {
        int sb = s0 + sch * 64;
        __syncthreads();
        for (int i = tid; i < MQ * 64; i += 128) {
            int m = i >> 6, ss = i & 63;
            tb[i] = g_tab[m * SQ + sb + ss];
        }
        __syncthreads();
        for (int ss = 0; ss < 64; ss++) {
            float acc = 0.f;
#pragma unroll
            for (int m = 1; m < MQ; m++) {
                float2 t = tb[m * 64 + ss];
                acc = fmaf(yr[m],  t.x, acc);
                acc = fmaf(-yi[m], t.y, acc);
            }
            g_xf[(b * SQ + sb + ss) * HQ + c] = (yr[0] + 2.f * acc) * (1.0f / (float)SQ);
        }
    }
}

// ---------------- 3xTF32 tensor-core GEMM: C[M,N] = A[M,K] @ W[N,K]^T ----------------
// BM=BN=64, BK=32, 128 threads (4 warps, 2x2 of 32x32 warp tiles)
// gmode 0: C = acc ; gmode 1: C = gelu(acc + bias[n])
__global__ void __launch_bounds__(128, 3)
k_gemm_tc(const float* __restrict__ Amat, const float* __restrict__ Wmat,
          float* __restrict__ Cmat, int Mdim, int Ndim, int Kdim,
          const float* __restrict__ biasPtr, int gmode) {
    __shared__ __align__(16) unsigned int shAhi[64 * 32];
    __shared__ __align__(16) unsigned int shAlo[64 * 32];
    __shared__ __align__(16) unsigned int shBhi[64 * 32];
    __shared__ __align__(16) unsigned int shBlo[64 * 32];

    const int tid  = threadIdx.x;
    const int lane = tid & 31;
    const int warpIdx = tid >> 5;
    const int wmoff = (warpIdx & 1) * 32;
    const int wnoff = (warpIdx >> 1) * 32;
    const int rowBase = blockIdx.x * 64;
    const int colBase = blockIdx.y * 64;

    const unsigned int adrAhi = (unsigned int)__cvta_generic_to_shared(shAhi);
    const unsigned int adrAlo = (unsigned int)__cvta_generic_to_shared(shAlo);
    const unsigned int adrBhi = (unsigned int)__cvta_generic_to_shared(shBhi);
    const unsigned int adrBlo = (unsigned int)__cvta_generic_to_shared(shBlo);

    const int stgRow = tid >> 3;   // + 16*ii
    const int stgCh  = tid & 7;
    const int arowA  = wmoff + (lane & 15);              // + fi*16
    const int achA   = lane >> 4;                        // chunk = 2*gi + this
    const int browB  = wnoff + ((lane >> 4) << 3) + (lane & 7);  // + pj*16
    const int bchB   = (lane >> 3) & 1;                  // chunk = 2*gi + this

    float acc[2][4][4];
#pragma unroll
    for (int fi = 0; fi < 2; fi++)
#pragma unroll
        for (int ji = 0; ji < 4; ji++)
#pragma unroll
            for (int ci = 0; ci < 4; ci++) acc[fi][ji][ci] = 0.0f;

    float4 regA[4];
    float4 regB[4];

    // -------- prologue: load k-slab 0 and stage it --------
#pragma unroll
    for (int ii = 0; ii < 4; ii++) {
        int rr = stgRow + ii * 16;
        regA[ii] = *(const float4*)&Amat[(size_t)(rowBase + rr) * Kdim + stgCh * 4];
        regB[ii] = *(const float4*)&Wmat[(size_t)(colBase + rr) * Kdim + stgCh * 4];
    }
#pragma unroll
    for (int ii = 0; ii < 4; ii++) {
        int rr = stgRow + ii * 16;
        int woff = rr * 32 + ((stgCh ^ (rr & 7)) << 2);
        uint4 pkAhi, pkAlo, pkBhi, pkBlo;
        pkAhi.x = f2tf32(regA[ii].x); pkAlo.x = f2tf32(regA[ii].x - __uint_as_float(pkAhi.x));
        pkAhi.y = f2tf32(regA[ii].y); pkAlo.y = f2tf32(regA[ii].y - __uint_as_float(pkAhi.y));
        pkAhi.z = f2tf32(regA[ii].z); pkAlo.z = f2tf32(regA[ii].z - __uint_as_float(pkAhi.z));
        pkAhi.w = f2tf32(regA[ii].w); pkAlo.w = f2tf32(regA[ii].w - __uint_as_float(pkAhi.w));
        pkBhi.x = f2tf32(regB[ii].x); pkBlo.x = f2tf32(regB[ii].x - __uint_as_float(pkBhi.x));
        pkBhi.y = f2tf32(regB[ii].y); pkBlo.y = f2tf32(regB[ii].y - __uint_as_float(pkBhi.y));
        pkBhi.z = f2tf32(regB[ii].z); pkBlo.z = f2tf32(regB[ii].z - __uint_as_float(pkBhi.z));
        pkBhi.w = f2tf32(regB[ii].w); pkBlo.w = f2tf32(regB[ii].w - __uint_as_float(pkBhi.w));
        *(uint4*)&shAhi[woff] = pkAhi;
        *(uint4*)&shAlo[woff] = pkAlo;
        *(uint4*)&shBhi[woff] = pkBhi;
        *(uint4*)&shBlo[woff] = pkBlo;
    }
    __syncthreads();

    for (int kpos = 0; kpos < Kdim; kpos += 32) {
        const int hasNext = (kpos + 32) < Kdim;
        if (hasNext) {
#pragma unroll
            for (int ii = 0; ii < 4; ii++) {
                int rr = stgRow + ii * 16;
                regA[ii] = *(const float4*)&Amat[(size_t)(rowBase + rr) * Kdim + kpos + 32 + stgCh * 4];
                regB[ii] = *(const float4*)&Wmat[(size_t)(colBase + rr) * Kdim + kpos + 32 + stgCh * 4];
            }
        }

#pragma unroll
        for (int gi = 0; gi < 4; gi++) {
            unsigned int fragAhi[2][4];
            unsigned int fragAlo[2][4];
            unsigned int fragBhi[4][2];
            unsigned int fragBlo[4][2];
#pragma unroll
            for (int fi = 0; fi < 2; fi++) {
                int rr = arowA + fi * 16;
                int chq = 2 * gi + achA;
                unsigned int byoff = (unsigned int)((rr * 32 + ((chq ^ (rr & 7)) << 2)) << 2);
                ldsm4(fragAhi[fi][0], fragAhi[fi][1], fragAhi[fi][2], fragAhi[fi][3],
                      adrAhi + byoff);
                ldsm4(fragAlo[fi][0], fragAlo[fi][1], fragAlo[fi][2], fragAlo[fi][3],
                      adrAlo + byoff);
            }
#pragma unroll
            for (int pj = 0; pj < 2; pj++) {
                int rr = browB + pj * 16;
                int chq = 2 * gi + bchB;
                unsigned int byoff = (unsigned int)((rr * 32 + ((chq ^ (rr & 7)) << 2)) << 2);
                unsigned int tqa[4];
                ldsm4(tqa[0], tqa[1], tqa[2], tqa[3], adrBhi + byoff);
                fragBhi[2 * pj + 0][0] = tqa[0];
                fragBhi[2 * pj + 0][1] = tqa[1];
                fragBhi[2 * pj + 1][0] = tqa[2];
                fragBhi[2 * pj + 1][1] = tqa[3];
                unsigned int tqb[4];
                ldsm4(tqb[0], tqb[1], tqb[2], tqb[3], adrBlo + byoff);
                fragBlo[2 * pj + 0][0] = tqb[0];
                fragBlo[2 * pj + 0][1] = tqb[1];
                fragBlo[2 * pj + 1][0] = tqb[2];
                fragBlo[2 * pj + 1][1] = tqb[3];
            }
#pragma unroll
            for (int fi = 0; fi < 2; fi++) {
#pragma unroll
                for (int ji = 0; ji < 4; ji++) {
                    mma_tf32(acc[fi][ji], fragAhi[fi], fragBhi[ji]);
                    mma_tf32(acc[fi][ji], fragAlo[fi], fragBhi[ji]);
                    mma_tf32(acc[fi][ji], fragAhi[fi], fragBlo[ji]);
                }
            }
        }

        if (hasNext) {
            __syncthreads();
#pragma unroll
            for (int ii = 0; ii < 4; ii++) {
                int rr = stgRow + ii * 16;
                int woff = rr * 32 + ((stgCh ^ (rr & 7)) << 2);
                uint4 pkAhi, pkAlo, pkBhi, pkBlo;
                pkAhi.x = f2tf32(regA[ii].x); pkAlo.x = f2tf32(regA[ii].x - __uint_as_float(pkAhi.x));
                pkAhi.y = f2tf32(regA[ii].y); pkAlo.y = f2tf32(regA[ii].y - __uint_as_float(pkAhi.y));
                pkAhi.z = f2tf32(regA[ii].z); pkAlo.z = f2tf32(regA[ii].z - __uint_as_float(pkAhi.z));
                pkAhi.w = f2tf32(regA[ii].w); pkAlo.w = f2tf32(regA[ii].w - __uint_as_float(pkAhi.w));
                pkBhi.x = f2tf32(regB[ii].x); pkBlo.x = f2tf32(regB[ii].x - __uint_as_float(pkBhi.x));
                pkBhi.y = f2tf32(regB[ii].y); pkBlo.y = f2tf32(regB[ii].y - __uint_as_float(pkBhi.y));
                pkBhi.z = f2tf32(regB[ii].z); pkBlo.z = f2tf32(regB[ii].z - __uint_as_float(pkBhi.z));
                pkBhi.w = f2tf32(regB[ii].w); pkBlo.w = f2tf32(regB[ii].w - __uint_as_float(pkBhi.w));
                *(uint4*)&shAhi[woff] = pkAhi;
                *(uint4*)&shAlo[woff] = pkAlo;
                *(uint4*)&shBhi[woff] = pkBhi;
                *(uint4*)&shBlo[woff] = pkBlo;
            }
            __syncthreads();
        }
    }

    // -------- epilogue --------
#pragma unroll
    for (int fi = 0; fi < 2; fi++) {
#pragma unroll
        for (int ji = 0; ji < 4; ji++) {
            int orow = rowBase + wmoff + fi * 16 + (lane >> 2);
            int ocol = colBase + wnoff + ji * 8 + (lane & 3) * 2;
            float outA = acc[fi][ji][0];
            float outB = acc[fi][ji][1];
            float outC = acc[fi][ji][2];
            float outD = acc[fi][ji][3];
            if (gmode == 1) {
                float biasLo = biasPtr[ocol];
                float biasHi = biasPtr[ocol + 1];
                outA = gelu_exact(outA + biasLo);
                outB = gelu_exact(outB + biasHi);
                outC = gelu_exact(outC + biasLo);
                outD = gelu_exact(outD + biasHi);
            }
            *(float2*)&Cmat[(size_t)orow * Ndim + ocol] = make_float2(outA, outB);
            *(float2*)&Cmat[(size_t)(orow + 8) * Ndim + ocol] = make_float2(outC, outD);
        }
    }
}

// ---------------- fused: y += conv_b + xf ; LayerNorm ; h = LN*g+b + h ----------------
__global__ void k_ln(const float* __restrict__ cb, const float* __restrict__ gg,
                     const float* __restrict__ bb) {
    int row = blockIdx.x, tid = threadIdx.x;
    float v[4], s = 0.f, s2 = 0.f;
#pragma unroll
    for (int i = 0; i < 4; i++) {
        int j = tid + i * 128;
        float t = g_y[(size_t)row * HQ + j] + g_xf[(size_t)row * HQ + j] + cb[j];
        v[i] = t; s += t; s2 += t * t;
    }
#pragma unroll
    for (int o = 16; o; o >>= 1) {
        s  += __shfl_xor_sync(0xffffffffu, s,  o);
        s2 += __shfl_xor_sync(0xffffffffu, s2, o);
    }
    __shared__ float red[64];
    int w = tid >> 5;
    if ((tid & 31) == 0) { red[w] = s; red[32 + w] = s2; }
    __syncthreads();
    float ts  = red[0] + red[1] + red[2] + red[3];
    float ts2 = red[32] + red[33] + red[34] + red[35];
    float mu  = ts * (1.f / HQ);
    float var = ts2 * (1.f / HQ) - mu * mu;
    float rinv = rsqrtf(var + 1e-5f);
#pragma unroll
    for (int i = 0; i < 4; i++) {
        int j = tid + i * 128;
        size_t idx = (size_t)row * HQ + j;
        g_h[idx] = (v[i] - mu) * rinv * gg[j] + bb[j] + g_h[idx];
    }
}

// ---------------- final projection to scalar ----------------
__global__ void k_op3(const float* __restrict__ w, const float* __restrict__ b3,
                      float* __restrict__ out) {
    int tid = threadIdx.x;
    int row = blockIdx.x * 4 + (tid >> 5);
    int lane = tid & 31;
    float s = 0.f;
#pragma unroll
    for (int i = 0; i < 4; i++) {
        int j = lane + i * 32;
        s += g_o2[(size_t)row * 128 + j] * w[j];
    }
#pragma unroll
    for (int o = 16; o; o >>= 1) s += __shfl_xor_sync(0xffffffffu, s, o);
    if (lane == 0) out[row] = s + b3[0];
}

// ---------------- mean over s ----------------
__global__ void k_mean() {
    int b = blockIdx.x >> 2;
    int c = (blockIdx.x & 3) * 128 + threadIdx.x;
    float s = 0.f;
    for (int ss = 0; ss < SQ; ss++) s += g_h[(size_t)(b * SQ + ss) * HQ + c];
    g_gf[b * HQ + c] = s * (1.f / SQ);
}

// ---------------- head: k1 = gelu(gf @ h1_w^T + h1_b) ----------------
__global__ void k_head1(const float* __restrict__ w, const float* __restrict__ bias) {
    int b = blockIdx.x, tid = threadIdx.x;
    int j = blockIdx.y * 128 + tid;
    __shared__ float sg[HQ];
    for (int i = tid; i < HQ; i += 128) sg[i] = g_gf[b * HQ + i];
    __syncthreads();
    const float4* w4 = (const float4*)(w + (size_t)j * HQ);
    float acc = 0.f;
    for (int c = 0; c < HQ / 4; c++) {
        float4 wv = w4[c];
        float4 gv = *(const float4*)&sg[c * 4];
        acc = fmaf(wv.x, gv.x, acc); acc = fmaf(wv.y, gv.y, acc);
        acc = fmaf(wv.z, gv.z, acc); acc = fmaf(wv.w, gv.w, acc);
    }
    g_k1[b * HQ + j] = gelu_exact(acc + bias[j]);
}

// ---------------- head: key_pred = sigmoid(k1 @ h2_w^T + h2_b) ----------------
__global__ void k_head2(const float* __restrict__ w, const float* __restrict__ bias,
                        float* __restrict__ out) {
    int b = blockIdx.x, tid = threadIdx.x;
    int j = blockIdx.y * 128 + tid;
    __shared__ float sk[HQ];
    for (int i = tid; i < HQ; i += 128) sk[i] = g_k1[b * HQ + i];
    __syncthreads();
    const float4* w4 = (const float4*)(w + (size_t)j * HQ);
    float acc = 0.f;
    for (int c = 0; c < HQ / 4; c++) {
        float4 wv = w4[c];
        float4 kv = *(const float4*)&sk[c * 4];
        acc = fmaf(wv.x, kv.x, acc); acc = fmaf(wv.y, kv.y, acc);
        acc = fmaf(wv.z, kv.z, acc); acc = fmaf(wv.w, kv.w, acc);
    }
    float t = acc + bias[j];
    out[BQ * SQ + b * KBQ + j] = 1.f / (1.f + expf(-t));
}

// ---------------- launch ----------------
extern "C" void kernel_launch(void* const* d_in, const int* in_sizes, int n_in,
                              void* d_out, int out_size) {
    const float* x      = (const float*)d_in[0];
    const float* in_w   = (const float*)d_in[1];
    const float* in_b   = (const float*)d_in[2];
    const float* fw_r   = (const float*)d_in[3];
    const float* fw_i   = (const float*)d_in[4];
    const float* conv_w = (const float*)d_in[5];
    const float* conv_b = (const float*)d_in[6];
    const float* ln_g   = (const float*)d_in[7];
    const float* ln_b   = (const float*)d_in[8];
    const float* op1_w  = (const float*)d_in[9];
    const float* op1_b  = (const float*)d_in[10];
    const float* op2_w  = (const float*)d_in[11];
    const float* op2_b  = (const float*)d_in[12];
    const float* op3_w  = (const float*)d_in[13];
    const float* op3_b  = (const float*)d_in[14];
    const float* h1_w   = (const float*)d_in[15];
    const float* h1_b   = (const float*)d_in[16];
    const float* h2_w   = (const float*)d_in[17];
    const float* h2_b   = (const float*)d_in[18];
    float* out = (float*)d_out;

    float *hp, *yp, *o1p, *o2p;
    cudaGetSymbolAddress((void**)&hp,  g_h);
    cudaGetSymbolAddress((void**)&yp,  g_y);
    cudaGetSymbolAddress((void**)&o1p, g_o1);
    cudaGetSymbolAddress((void**)&o2p, g_o2);

    k_tab<<<(MQ * SQ + 255) / 256, 256>>>();
    k_init<<<(BQ * SQ * HQ + 255) / 256, 256>>>(x, in_w, in_b);

    for (int l = 0; l < LQ; l++) {
        k_dftf<<<dim3(BQ * (HQ / 128), SPLITS), 128>>>();
        k_dftred<<<(BQ * MQ * HQ + 255) / 256, 256>>>();
        k_spec<<<dim3(MQ, HQ / 128), 128>>>(fw_r + (size_t)l * MQ * HQ * HQ,
                                            fw_i + (size_t)l * MQ * HQ * HQ);
        k_idft<<<dim3(SQ / 256, BQ * 4), 128>>>();
        k_gemm_tc<<<dim3(BQ * SQ / 64, HQ / 64), 128>>>(hp, conv_w + (size_t)l * HQ * HQ,
                                                        yp, BQ * SQ, HQ, HQ, (const float*)0, 0);
        k_ln<<<BQ * SQ, 128>>>(conv_b + l * HQ, ln_g + l * HQ, ln_b + l * HQ);
    }

    // output projection: H -> H/2 -> H/4 -> 1 (bias+gelu fused into epilogues)
    k_gemm_tc<<<dim3(BQ * SQ / 64, (HQ / 2) / 64), 128>>>(hp, op1_w, o1p,
                                                          BQ * SQ, HQ / 2, HQ, op1_b, 1);
    k_gemm_tc<<<dim3(BQ * SQ / 64, (HQ / 4) / 64), 128>>>(o1p, op2_w, o2p,
                                                          BQ * SQ, HQ / 4, HQ / 2, op2_b, 1);
    k_op3<<<BQ * SQ / 4, 128>>>(op3_w, op3_b, out);

    // cryptanalytic head
    k_mean<<<BQ * 4, 128>>>();
    k_head1<<<dim3(BQ, HQ / 128), 128>>>(h1_w, h1_b);
    k_head2<<<dim3(BQ, KBQ / 128), 128>>>(h2_w, h2_b, out);
}